// round 2
// baseline (speedup 1.0000x reference)
#include <cuda_runtime.h>
#include <math.h>

#define TL 1024
#define TD 64
#define TM 64
#define TH 8
#define TBH 64
#define FDM (TBH*TD*TM)   // 262144

// ---------------- device scratch (static; no allocations) ----------------
__device__ float g_cosT[TL*TM];   // [t][m]
__device__ float g_sinT[TL*TM];
__device__ float g_cosM[TM*TL];   // [m][t]
__device__ float g_sinM[TM*TL];
// forward DFT results as double-float (hi, lo), split over 2 t-phases
__device__ float g_qf_re [2*FDM];
__device__ float g_qf_im [2*FDM];
__device__ float g_qf_rel[2*FDM];
__device__ float g_qf_iml[2*FDM];
__device__ float g_kf_re [2*FDM];
__device__ float g_kf_im [2*FDM];
__device__ float g_kf_rel[2*FDM];
__device__ float g_kf_iml[2*FDM];
__device__ float g_ctx_re[FDM];   // [bh][mq][d]
__device__ float g_ctx_im[FDM];
__device__ float g_wt_re[TH*TM*TD*TD]; // [h][q][i][j]
__device__ float g_wt_im[TH*TM*TD*TD];
__device__ float g_c2_re[FDM];    // [bh][mq][j]
__device__ float g_c2_im[FDM];

// ---------------- compensated arithmetic helpers ----------------
// Neumaier add of value v into (s, e)
__device__ __forceinline__ void nAdd(float v, float& s, float& e) {
    float t = s + v;
    e += (fabsf(s) >= fabsf(v)) ? ((s - t) + v) : ((v - t) + s);
    s = t;
}
// TwoProd(a,b) accumulated into (s, e) with Neumaier
__device__ __forceinline__ void dfAddProd(float a, float b, float& s, float& e) {
    float p  = a * b;
    float pe = fmaf(a, b, -p);
    float t  = s + p;
    float r  = (fabsf(s) >= fabsf(p)) ? ((s - t) + p) : ((p - t) + s);
    s = t;
    e += r + pe;
}
// TwoSum of a+b -> (h, err)
__device__ __forceinline__ float tsumErr(float a, float b, float h) {
    return (fabsf(a) >= fabsf(b)) ? ((a - h) + b) : ((b - h) + a);
}

// ---------------- K0: twiddle tables ----------------
__global__ void k_twiddle() {
    int idx = blockIdx.x * blockDim.x + threadIdx.x;   // over TM*TL = 65536
    int m = idx >> 10;
    int t = idx & 1023;
    int r = (m * t) & 1023;                            // mt mod 1024
    float s, c;
    sincospif((float)r * (1.0f / 512.0f), &s, &c);     // angle = 2*pi*m*t/1024
    g_cosM[m * TL + t] = c;
    g_sinM[m * TL + t] = s;
    g_cosT[t * TM + m] = c;
    g_sinT[t * TM + m] = s;
}

// ---------------- K0b: weight transpose [h][i][j][q] -> [h][q][i*64+j] ----------------
__global__ void k_wtrans(const float* __restrict__ wr, const float* __restrict__ wi) {
    __shared__ float tr[32][33];
    __shared__ float ti[32][33];
    int h   = blockIdx.z;
    int ij0 = blockIdx.x * 32;
    int q0  = blockIdx.y * 32;
    int tx = threadIdx.x, ty = threadIdx.y;
    #pragma unroll
    for (int rr = ty; rr < 32; rr += 8) {
        tr[rr][tx] = wr[((size_t)h * 4096 + ij0 + rr) * 64 + q0 + tx];
        ti[rr][tx] = wi[((size_t)h * 4096 + ij0 + rr) * 64 + q0 + tx];
    }
    __syncthreads();
    #pragma unroll
    for (int rr = ty; rr < 32; rr += 8) {
        g_wt_re[((size_t)h * 64 + q0 + rr) * 4096 + ij0 + tx] = tr[tx][rr];
        g_wt_im[((size_t)h * 64 + q0 + rr) * 4096 + ij0 + tx] = ti[tx][rr];
    }
}

// ---------------- K1: forward partial DFT (64 modes), compensated ----------------
// grid (BH, 2 src, 2 t-phase), 256 threads, 4x4 register tile per thread.
// Plain FMA within 32-t sub-chunks, Neumaier merge -> (hi, lo) double-float result.
__global__ __launch_bounds__(256) void k_fdft(const float* __restrict__ q,
                                              const float* __restrict__ k) {
    int bh = blockIdx.x;
    int srcsel = blockIdx.y;
    int ph = blockIdx.z;
    const float* src = (srcsel == 0 ? q : k) + (size_t)bh * TL * TD + (size_t)ph * 512 * TD;
    size_t ob = (size_t)ph * FDM + (size_t)bh * (TD * TM);
    float* drh = (srcsel == 0 ? g_qf_re  : g_kf_re ) + ob;
    float* dih = (srcsel == 0 ? g_qf_im  : g_kf_im ) + ob;
    float* drl = (srcsel == 0 ? g_qf_rel : g_kf_rel) + ob;
    float* dil = (srcsel == 0 ? g_qf_iml : g_kf_iml) + ob;
    const float* ct = g_cosT + ph * 512 * TM;
    const float* st = g_sinT + ph * 512 * TM;

    __shared__ float q_s[64 * 64];   // [t][d]
    __shared__ float c_s[64 * 64];   // [t][m]
    __shared__ float s_s[64 * 64];

    int tid = threadIdx.x;
    int m0 = (tid & 15) * 4;
    int d0 = (tid >> 4) * 4;

    float sr[4][4], er[4][4], si_[4][4], ei[4][4];   // main (hi) + comp (lo)
    float lar[4][4], lai[4][4];                      // chunk-local
    #pragma unroll
    for (int a = 0; a < 4; a++)
        #pragma unroll
        for (int b = 0; b < 4; b++) {
            sr[a][b] = 0.f; er[a][b] = 0.f; si_[a][b] = 0.f; ei[a][b] = 0.f;
            lar[a][b] = 0.f; lai[a][b] = 0.f;
        }

    for (int tt = 0; tt < 512; tt += 64) {
        __syncthreads();
        #pragma unroll
        for (int i = 0; i < 4; i++) {
            int idx = tid + i * 256;
            ((float4*)q_s)[idx] = ((const float4*)(src + tt * TD))[idx];
            ((float4*)c_s)[idx] = ((const float4*)(ct + tt * TM))[idx];
            ((float4*)s_s)[idx] = ((const float4*)(st + tt * TM))[idx];
        }
        __syncthreads();
        #pragma unroll
        for (int half = 0; half < 2; half++) {
            #pragma unroll 4
            for (int t = half * 32; t < half * 32 + 32; t++) {
                float4 qv = *(float4*)(q_s + t * 64 + d0);
                float4 cv = *(float4*)(c_s + t * 64 + m0);
                float4 sv = *(float4*)(s_s + t * 64 + m0);
                float qq[4] = {qv.x, qv.y, qv.z, qv.w};
                float cc[4] = {cv.x, cv.y, cv.z, cv.w};
                float ss[4] = {sv.x, sv.y, sv.z, sv.w};
                #pragma unroll
                for (int a = 0; a < 4; a++)
                    #pragma unroll
                    for (int b = 0; b < 4; b++) {
                        lar[a][b] = fmaf(qq[a], cc[b], lar[a][b]);
                        lai[a][b] = fmaf(-qq[a], ss[b], lai[a][b]);
                    }
            }
            // Neumaier merge of sub-chunk partials into main accumulators
            #pragma unroll
            for (int a = 0; a < 4; a++)
                #pragma unroll
                for (int b = 0; b < 4; b++) {
                    nAdd(lar[a][b], sr[a][b], er[a][b]);
                    nAdd(lai[a][b], si_[a][b], ei[a][b]);
                    lar[a][b] = 0.f; lai[a][b] = 0.f;
                }
        }
    }
    #pragma unroll
    for (int a = 0; a < 4; a++)
        #pragma unroll
        for (int b = 0; b < 4; b++) {
            drh[(d0 + a) * TM + m0 + b] = sr[a][b];
            dih[(d0 + a) * TM + m0 + b] = si_[a][b];
            drl[(d0 + a) * TM + m0 + b] = er[a][b];
            dil[(d0 + a) * TM + m0 + b] = ei[a][b];
        }
}

// ---------------- K2: scores (compensated) -> complex tanh -> context ----------------
// one block per bh; 160KB dynamic smem.
__global__ __launch_bounds__(256) void k_scores() {
    int bh = blockIdx.x;
    extern __shared__ float smArr[];
    float* sKr  = smArr;             // K hi [d][m]
    float* sKi  = smArr + 4096;
    float* sKrl = smArr + 8192;      // K lo [d][m]
    float* sKil = smArr + 12288;
    float* sKTr = smArr + 16384;     // K hi transposed [m][d]
    float* sKTi = smArr + 20480;
    float* sQr  = smArr + 24576;     // Q hi [d][m]; reused as At re [mk][mq]
    float* sQi  = smArr + 28672;     //               reused as At im
    float* sQrl = smArr + 32768;     // Q lo
    float* sQil = smArr + 36864;
    int tid = threadIdx.x;
    int base = bh * 4096;

    for (int i = tid; i < 4096; i += 256) {
        // combine the two t-phase partials with TwoSum
        float a, b, h;
        a = g_kf_re[base + i]; b = g_kf_re[FDM + base + i]; h = a + b;
        float krl = g_kf_rel[base + i] + g_kf_rel[FDM + base + i] + tsumErr(a, b, h);
        float krh = h;
        a = g_kf_im[base + i]; b = g_kf_im[FDM + base + i]; h = a + b;
        float kil = g_kf_iml[base + i] + g_kf_iml[FDM + base + i] + tsumErr(a, b, h);
        float kih = h;
        sKr[i] = krh; sKi[i] = kih; sKrl[i] = krl; sKil[i] = kil;
        int d = i >> 6, m = i & 63;
        sKTr[m * 64 + d] = krh + krl;
        sKTi[m * 64 + d] = kih + kil;

        a = g_qf_re[base + i]; b = g_qf_re[FDM + base + i]; h = a + b;
        sQrl[i] = g_qf_rel[base + i] + g_qf_rel[FDM + base + i] + tsumErr(a, b, h);
        sQr[i] = h;
        a = g_qf_im[base + i]; b = g_qf_im[FDM + base + i]; h = a + b;
        sQil[i] = g_qf_iml[base + i] + g_qf_iml[FDM + base + i] + tsumErr(a, b, h);
        sQi[i] = h;
    }
    __syncthreads();

    int mq0 = (tid >> 4) * 4;
    int mk0 = (tid & 15) * 4;

    // phase A: scores[mq][mk] = sum_d Qf[d][mq]*Kf[d][mk], compensated complex GEMM
    float srA[4][4], erA[4][4], siA[4][4], eiA[4][4];
    #pragma unroll
    for (int a = 0; a < 4; a++)
        #pragma unroll
        for (int b = 0; b < 4; b++) { srA[a][b]=0.f; erA[a][b]=0.f; siA[a][b]=0.f; eiA[a][b]=0.f; }

    for (int d = 0; d < 64; d++) {
        float4 qrh4 = *(float4*)(sQr  + d * 64 + mq0);
        float4 qih4 = *(float4*)(sQi  + d * 64 + mq0);
        float4 qrl4 = *(float4*)(sQrl + d * 64 + mq0);
        float4 qil4 = *(float4*)(sQil + d * 64 + mq0);
        float4 krh4 = *(float4*)(sKr  + d * 64 + mk0);
        float4 kih4 = *(float4*)(sKi  + d * 64 + mk0);
        float4 krl4 = *(float4*)(sKrl + d * 64 + mk0);
        float4 kil4 = *(float4*)(sKil + d * 64 + mk0);
        float qrh[4] = {qrh4.x, qrh4.y, qrh4.z, qrh4.w};
        float qih[4] = {qih4.x, qih4.y, qih4.z, qih4.w};
        float qrl[4] = {qrl4.x, qrl4.y, qrl4.z, qrl4.w};
        float qil[4] = {qil4.x, qil4.y, qil4.z, qil4.w};
        float krh[4] = {krh4.x, krh4.y, krh4.z, krh4.w};
        float kih[4] = {kih4.x, kih4.y, kih4.z, kih4.w};
        float krl[4] = {krl4.x, krl4.y, krl4.z, krl4.w};
        float kil[4] = {kil4.x, kil4.y, kil4.z, kil4.w};
        #pragma unroll
        for (int a = 0; a < 4; a++)
            #pragma unroll
            for (int b = 0; b < 4; b++) {
                // re += qr*kr - qi*ki
                dfAddProd(qrh[a],  krh[b], srA[a][b], erA[a][b]);
                dfAddProd(-qih[a], kih[b], srA[a][b], erA[a][b]);
                erA[a][b] = fmaf(qrh[a], krl[b], erA[a][b]);
                erA[a][b] = fmaf(qrl[a], krh[b], erA[a][b]);
                erA[a][b] = fmaf(-qih[a], kil[b], erA[a][b]);
                erA[a][b] = fmaf(-qil[a], kih[b], erA[a][b]);
                // im += qr*ki + qi*kr
                dfAddProd(qrh[a], kih[b], siA[a][b], eiA[a][b]);
                dfAddProd(qih[a], krh[b], siA[a][b], eiA[a][b]);
                eiA[a][b] = fmaf(qrh[a], kil[b], eiA[a][b]);
                eiA[a][b] = fmaf(qrl[a], kih[b], eiA[a][b]);
                eiA[a][b] = fmaf(qih[a], krl[b], eiA[a][b]);
                eiA[a][b] = fmaf(qil[a], krh[b], eiA[a][b]);
            }
    }

    // complex tanh (stable form)
    float tr[4][4], tim[4][4];
    #pragma unroll
    for (int a = 0; a < 4; a++)
        #pragma unroll
        for (int b = 0; b < 4; b++) {
            float x2 = 2.f * (srA[a][b] + erA[a][b]);
            float y2 = 2.f * (siA[a][b] + eiA[a][b]);
            float rr, im;
            if (fabsf(x2) > 30.f) {
                rr = x2 > 0.f ? 1.f : -1.f;
                im = 0.f;
            } else {
                float den = coshf(x2) + cosf(y2);
                rr = sinhf(x2) / den;
                im = sinf(y2) / den;
            }
            tr[a][b] = rr; tim[a][b] = im;
        }
    __syncthreads();
    // store attn transposed: At[mk][mq]
    #pragma unroll
    for (int a = 0; a < 4; a++)
        #pragma unroll
        for (int b = 0; b < 4; b++) {
            sQr[(mk0 + b) * 64 + mq0 + a] = tr[a][b];
            sQi[(mk0 + b) * 64 + mq0 + a] = tim[a][b];
        }
    __syncthreads();

    // phase B: ctx[mq][d] = sum_mk attn[mq][mk]*Kf[d][mk]  (plain fp32 is plenty)
    int d0 = mk0;
    float cr[4][4], ci[4][4];
    #pragma unroll
    for (int a = 0; a < 4; a++)
        #pragma unroll
        for (int b = 0; b < 4; b++) { cr[a][b] = 0.f; ci[a][b] = 0.f; }

    for (int mk = 0; mk < 64; mk++) {
        float4 ar4 = *(float4*)(sQr + mk * 64 + mq0);
        float4 ai4 = *(float4*)(sQi + mk * 64 + mq0);
        float4 kr4 = *(float4*)(sKTr + mk * 64 + d0);
        float4 ki4 = *(float4*)(sKTi + mk * 64 + d0);
        float arv[4] = {ar4.x, ar4.y, ar4.z, ar4.w};
        float aiv[4] = {ai4.x, ai4.y, ai4.z, ai4.w};
        float krv[4] = {kr4.x, kr4.y, kr4.z, kr4.w};
        float kiv[4] = {ki4.x, ki4.y, ki4.z, ki4.w};
        #pragma unroll
        for (int a = 0; a < 4; a++)
            #pragma unroll
            for (int b = 0; b < 4; b++) {
                cr[a][b] += arv[a] * krv[b] - aiv[a] * kiv[b];
                ci[a][b] += arv[a] * kiv[b] + aiv[a] * krv[b];
            }
    }
    #pragma unroll
    for (int a = 0; a < 4; a++)
        #pragma unroll
        for (int b = 0; b < 4; b++) {
            g_ctx_re[base + (mq0 + a) * 64 + d0 + b] = cr[a][b];
            g_ctx_im[base + (mq0 + a) * 64 + d0 + b] = ci[a][b];
        }
}

// ---------------- K3: per-mode complex weight mix ----------------
__global__ __launch_bounds__(256) void k_wmix() {
    int bid = blockIdx.x;
    int h = bid >> 6, qm = bid & 63;
    __shared__ float wr_s[4096];
    __shared__ float wi_s[4096];
    __shared__ float cvr[8][64];
    __shared__ float cvi[8][64];
    int tid = threadIdx.x;
    const float* wrp = g_wt_re + ((size_t)h * 64 + qm) * 4096;
    const float* wip = g_wt_im + ((size_t)h * 64 + qm) * 4096;
    #pragma unroll
    for (int i = 0; i < 4; i++) {
        ((float4*)wr_s)[tid + i * 256] = ((const float4*)wrp)[tid + i * 256];
        ((float4*)wi_s)[tid + i * 256] = ((const float4*)wip)[tid + i * 256];
    }
    for (int i = tid; i < 512; i += 256) {
        int b = i >> 6, ii = i & 63;
        int bh = b * TH + h;
        cvr[b][ii] = g_ctx_re[(bh * 64 + qm) * 64 + ii];
        cvi[b][ii] = g_ctx_im[(bh * 64 + qm) * 64 + ii];
    }
    __syncthreads();
    int b4 = tid >> 6;
    int j = tid & 63;
    #pragma unroll
    for (int bb = 0; bb < 2; bb++) {
        int b = bb * 4 + b4;
        float re = 0.f, im = 0.f;
        #pragma unroll 8
        for (int i = 0; i < 64; i++) {
            float wr = wr_s[i * 64 + j];
            float wi = wi_s[i * 64 + j];
            float crv = cvr[b][i];
            float civ = cvi[b][i];
            re += crv * wr - civ * wi;
            im += crv * wi + civ * wr;
        }
        int bh = b * TH + h;
        g_c2_re[(bh * 64 + qm) * 64 + j] = re;
        g_c2_im[(bh * 64 + qm) * 64 + j] = im;
    }
}

// ---------------- K4: sparse irfft (64 modes -> 1024 samples) ----------------
__global__ __launch_bounds__(256) void k_irfft(float* __restrict__ out) {
    int bh = blockIdx.x;
    int tbase = blockIdx.y * 128;
    extern __shared__ float smArr[];
    float* ar_s = smArr;          // [m][d]
    float* ai_s = smArr + 4096;
    float* c_s  = smArr + 8192;   // [m][128]
    float* s_s  = smArr + 16384;
    int tid = threadIdx.x;

    #pragma unroll
    for (int i = 0; i < 4; i++) {
        int idx = tid + i * 256;
        ((float4*)ar_s)[idx] = ((const float4*)(g_c2_re + bh * 4096))[idx];
        ((float4*)ai_s)[idx] = ((const float4*)(g_c2_im + bh * 4096))[idx];
    }
    #pragma unroll
    for (int i = 0; i < 8; i++) {
        int idx = tid + i * 256;          // float4 index over 64*128 floats
        int m = idx >> 5, c4 = idx & 31;
        ((float4*)c_s)[idx] = *(const float4*)(g_cosM + m * TL + tbase + c4 * 4);
        ((float4*)s_s)[idx] = *(const float4*)(g_sinM + m * TL + tbase + c4 * 4);
    }
    __syncthreads();

    int tx = tid & 31, ty = tid >> 5;
    int t0 = tx * 4, d0 = ty * 8;

    float acc[8][4];
    #pragma unroll
    for (int a = 0; a < 8; a++)
        #pragma unroll
        for (int b = 0; b < 4; b++) acc[a][b] = 0.f;

    for (int m = 1; m < 64; m++) {
        float4 cv = *(float4*)(c_s + m * 128 + t0);
        float4 sv = *(float4*)(s_s + m * 128 + t0);
        float4 arA = *(float4*)(ar_s + m * 64 + d0);
        float4 arB = *(float4*)(ar_s + m * 64 + d0 + 4);
        float4 aiA = *(float4*)(ai_s + m * 64 + d0);
        float4 aiB = *(float4*)(ai_s + m * 64 + d0 + 4);
        float arr[8] = {arA.x, arA.y, arA.z, arA.w, arB.x, arB.y, arB.z, arB.w};
        float aii[8] = {aiA.x, aiA.y, aiA.z, aiA.w, aiB.x, aiB.y, aiB.z, aiB.w};
        float cc[4] = {cv.x, cv.y, cv.z, cv.w};
        float ss[4] = {sv.x, sv.y, sv.z, sv.w};
        #pragma unroll
        for (int a = 0; a < 8; a++)
            #pragma unroll
            for (int b = 0; b < 4; b++)
                acc[a][b] += arr[a] * cc[b] - aii[a] * ss[b];
    }

    const float C0 = 1.0f / 268435456.0f;  // 1/(1024*512*512)
    const float C2 = 2.0f * C0;
    #pragma unroll
    for (int a = 0; a < 8; a++) {
        float a0 = ar_s[d0 + a];  // m=0 row; imag of bin 0 dropped by irfft
        float4 o;
        o.x = fmaf(C2, acc[a][0], C0 * a0);
        o.y = fmaf(C2, acc[a][1], C0 * a0);
        o.z = fmaf(C2, acc[a][2], C0 * a0);
        o.w = fmaf(C2, acc[a][3], C0 * a0);
        *(float4*)(out + ((size_t)bh * 64 + d0 + a) * 1024 + tbase + t0) = o;
    }
}

// ---------------- launch ----------------
extern "C" void kernel_launch(void* const* d_in, const int* in_sizes, int n_in,
                              void* d_out, int out_size) {
    const float* q  = (const float*)d_in[0];
    const float* k  = (const float*)d_in[1];
    const float* wr = (const float*)d_in[3];
    const float* wi = (const float*)d_in[4];
    float* out = (float*)d_out;
    (void)in_sizes; (void)n_in; (void)out_size;

    cudaFuncSetAttribute(k_scores, cudaFuncAttributeMaxDynamicSharedMemorySize, 164 * 1024);
    cudaFuncSetAttribute(k_irfft,  cudaFuncAttributeMaxDynamicSharedMemorySize, 96 * 1024);

    k_twiddle<<<256, 256>>>();
    k_wtrans<<<dim3(128, 2, TH), dim3(32, 8)>>>(wr, wi);
    k_fdft<<<dim3(TBH, 2, 2), 256>>>(q, k);
    k_scores<<<TBH, 256, 160 * 1024>>>();
    k_wmix<<<TH * TM, 256>>>();
    k_irfft<<<dim3(TBH, 8), 256, 96 * 1024>>>(out);
}

// round 4
// speedup vs baseline: 1.2219x; 1.2219x over previous
#include <cuda_runtime.h>
#include <math.h>

#define TL 1024
#define TD 64
#define TM 64
#define TH 8
#define TBH 64
#define FDM (TBH*TD*TM)   // 262144

typedef unsigned long long ull;

// ---------------- device scratch (static; no allocations) ----------------
__device__ float g_cosT[TL*TM];   // [t][m]
__device__ float g_sinT[TL*TM];
__device__ float g_cosM[TM*TL];   // [m][t]
__device__ float g_sinM[TM*TL];
// forward DFT results as double-float (hi, lo), split over 2 t-phases
__device__ float g_qf_re [2*FDM];
__device__ float g_qf_im [2*FDM];
__device__ float g_qf_rel[2*FDM];
__device__ float g_qf_iml[2*FDM];
__device__ float g_kf_re [2*FDM];
__device__ float g_kf_im [2*FDM];
__device__ float g_kf_rel[2*FDM];
__device__ float g_kf_iml[2*FDM];
__device__ float g_ctx_re[FDM];   // [bh][mq][d]
__device__ float g_ctx_im[FDM];
__device__ float g_wt_re[TH*TM*TD*TD]; // [h][q][i][j]
__device__ float g_wt_im[TH*TM*TD*TD];
__device__ float g_c2_re[FDM];    // [bh][mq][j]
__device__ float g_c2_im[FDM];

// ---------------- packed f32x2 helpers ----------------
__device__ __forceinline__ void fma2(ull& acc, ull a, ull b) {
    asm("fma.rn.f32x2 %0, %1, %2, %0;" : "+l"(acc) : "l"(a), "l"(b));
}
__device__ __forceinline__ ull pk2(float lo, float hi) {
    ull r;
    asm("mov.b64 %0, {%1, %2};" : "=l"(r) : "f"(lo), "f"(hi));
    return r;
}
__device__ __forceinline__ void upk2(ull v, float& lo, float& hi) {
    asm("mov.b64 {%0, %1}, %2;" : "=f"(lo), "=f"(hi) : "l"(v));
}

// ---------------- compensated arithmetic helpers ----------------
__device__ __forceinline__ void nAdd(float v, float& s, float& e) {
    float t = s + v;
    e += (fabsf(s) >= fabsf(v)) ? ((s - t) + v) : ((v - t) + s);
    s = t;
}
__device__ __forceinline__ void dfAddProd(float a, float b, float& s, float& e) {
    float p  = a * b;
    float pe = fmaf(a, b, -p);
    float t  = s + p;
    float r  = (fabsf(s) >= fabsf(p)) ? ((s - t) + p) : ((p - t) + s);
    s = t;
    e += r + pe;
}
__device__ __forceinline__ float tsumErr(float a, float b, float h) {
    return (fabsf(a) >= fabsf(b)) ? ((a - h) + b) : ((b - h) + a);
}

// ---------------- K0: twiddle tables ----------------
__global__ void k_twiddle() {
    int idx = blockIdx.x * blockDim.x + threadIdx.x;   // over TM*TL = 65536
    int m = idx >> 10;
    int t = idx & 1023;
    int r = (m * t) & 1023;
    float s, c;
    sincospif((float)r * (1.0f / 512.0f), &s, &c);
    g_cosM[m * TL + t] = c;
    g_sinM[m * TL + t] = s;
    g_cosT[t * TM + m] = c;
    g_sinT[t * TM + m] = s;
}

// ---------------- K0b: weight transpose [h][i][j][q] -> [h][q][i*64+j] ----------------
__global__ void k_wtrans(const float* __restrict__ wr, const float* __restrict__ wi) {
    __shared__ float tr[32][33];
    __shared__ float ti[32][33];
    int h   = blockIdx.z;
    int ij0 = blockIdx.x * 32;
    int q0  = blockIdx.y * 32;
    int tx = threadIdx.x, ty = threadIdx.y;
    #pragma unroll
    for (int rr = ty; rr < 32; rr += 8) {
        tr[rr][tx] = wr[((size_t)h * 4096 + ij0 + rr) * 64 + q0 + tx];
        ti[rr][tx] = wi[((size_t)h * 4096 + ij0 + rr) * 64 + q0 + tx];
    }
    __syncthreads();
    #pragma unroll
    for (int rr = ty; rr < 32; rr += 8) {
        g_wt_re[((size_t)h * 64 + q0 + rr) * 4096 + ij0 + tx] = tr[tx][rr];
        g_wt_im[((size_t)h * 64 + q0 + rr) * 4096 + ij0 + tx] = ti[tx][rr];
    }
}

// ---------------- K1: forward partial DFT (64 modes), compensated ----------------
// BIT-EXACT replica of the R2 (passing) kernel's per-(d,m) FMA sequence:
// plain FMA within 32-t sub-chunks, Neumaier merge -> (hi, lo) result.
// Speedup: fma.rn.f32x2 packs mode-pairs (m, m+1); each lane executes the
// identical IEEE op sequence as R2's scalar code. sin table is negated at
// smem-load so fma(q, -s) replaces fma(-q, s) (exactly equal results).
__global__ __launch_bounds__(256) void k_fdft(const float* __restrict__ q,
                                              const float* __restrict__ k) {
    int bh = blockIdx.x;
    int srcsel = blockIdx.y;
    int ph = blockIdx.z;
    const float* src = (srcsel == 0 ? q : k) + (size_t)bh * TL * TD + (size_t)ph * 512 * TD;
    size_t ob = (size_t)ph * FDM + (size_t)bh * (TD * TM);
    float* drh = (srcsel == 0 ? g_qf_re  : g_kf_re ) + ob;
    float* dih = (srcsel == 0 ? g_qf_im  : g_kf_im ) + ob;
    float* drl = (srcsel == 0 ? g_qf_rel : g_kf_rel) + ob;
    float* dil = (srcsel == 0 ? g_qf_iml : g_kf_iml) + ob;
    const float* ct = g_cosT + ph * 512 * TM;
    const float* st = g_sinT + ph * 512 * TM;

    __shared__ float q_s[64 * 64];   // [t][d]
    __shared__ float c_s[64 * 64];   // [t][m]
    __shared__ float s_s[64 * 64];   // [t][m], NEGATED sin

    int tid = threadIdx.x;
    int m0 = (tid & 15) * 4;
    int d0 = (tid >> 4) * 4;

    ull lar2[4][2], lai2[4][2];                      // chunk-local packed (m, m+1)
    float sr[4][4], er[4][4], si_[4][4], ei[4][4];   // main (hi) + comp (lo)
    #pragma unroll
    for (int a = 0; a < 4; a++) {
        #pragma unroll
        for (int b2 = 0; b2 < 2; b2++) { lar2[a][b2] = 0ULL; lai2[a][b2] = 0ULL; }
        #pragma unroll
        for (int b = 0; b < 4; b++) { sr[a][b]=0.f; er[a][b]=0.f; si_[a][b]=0.f; ei[a][b]=0.f; }
    }

    for (int tt = 0; tt < 512; tt += 64) {
        __syncthreads();
        #pragma unroll
        for (int i = 0; i < 4; i++) {
            int idx = tid + i * 256;
            ((float4*)q_s)[idx] = ((const float4*)(src + tt * TD))[idx];
            ((float4*)c_s)[idx] = ((const float4*)(ct + tt * TM))[idx];
            float4 sv = ((const float4*)(st + tt * TM))[idx];
            sv.x = -sv.x; sv.y = -sv.y; sv.z = -sv.z; sv.w = -sv.w;
            ((float4*)s_s)[idx] = sv;
        }
        __syncthreads();
        #pragma unroll
        for (int half = 0; half < 2; half++) {
            #pragma unroll 4
            for (int t = half * 32; t < half * 32 + 32; t++) {
                float4 qv = *(float4*)(q_s + t * 64 + d0);
                ulonglong2 cc = *(ulonglong2*)(c_s + t * 64 + m0);
                ulonglong2 ns = *(ulonglong2*)(s_s + t * 64 + m0);
                ull qq2[4] = {pk2(qv.x, qv.x), pk2(qv.y, qv.y),
                              pk2(qv.z, qv.z), pk2(qv.w, qv.w)};
                ull c2[2] = {cc.x, cc.y};
                ull s2[2] = {ns.x, ns.y};
                #pragma unroll
                for (int a = 0; a < 4; a++)
                    #pragma unroll
                    for (int b2 = 0; b2 < 2; b2++) {
                        fma2(lar2[a][b2], qq2[a], c2[b2]);   // lane: fma(q, cos)
                        fma2(lai2[a][b2], qq2[a], s2[b2]);   // lane: fma(q, -sin)
                    }
            }
            // Neumaier merge of sub-chunk partials (same per-accumulator order as R2)
            #pragma unroll
            for (int a = 0; a < 4; a++)
                #pragma unroll
                for (int b2 = 0; b2 < 2; b2++) {
                    float lo, hi;
                    upk2(lar2[a][b2], lo, hi);
                    nAdd(lo, sr[a][2*b2],   er[a][2*b2]);
                    nAdd(hi, sr[a][2*b2+1], er[a][2*b2+1]);
                    upk2(lai2[a][b2], lo, hi);
                    nAdd(lo, si_[a][2*b2],   ei[a][2*b2]);
                    nAdd(hi, si_[a][2*b2+1], ei[a][2*b2+1]);
                    lar2[a][b2] = 0ULL; lai2[a][b2] = 0ULL;
                }
        }
    }
    #pragma unroll
    for (int a = 0; a < 4; a++)
        #pragma unroll
        for (int b = 0; b < 4; b++) {
            drh[(d0 + a) * TM + m0 + b] = sr[a][b];
            dih[(d0 + a) * TM + m0 + b] = si_[a][b];
            drl[(d0 + a) * TM + m0 + b] = er[a][b];
            dil[(d0 + a) * TM + m0 + b] = ei[a][b];
        }
}

// ---------------- K2: scores (compensated) -> complex tanh -> context ----------------
// grid (4 mq-chunks, BH); 112KB smem -> 2 blocks/SM. Phase A per-(mq,mk) op
// sequence is operand/order-identical to the R2 passing kernel.
__global__ __launch_bounds__(256, 2) void k_scores() {
    int c0 = blockIdx.x * 16;
    int bh = blockIdx.y;
    extern __shared__ float sm[];
    float* sKr  = sm;                // K hi [d][m]   4096
    float* sKi  = sm + 4096;
    float* sKrl = sm + 8192;         // K lo [d][m]
    float* sKil = sm + 12288;
    float* sKTr = sm + 16384;        // K (hi+lo) transposed [m][d]
    float* sKTi = sm + 20480;
    float* sQr  = sm + 24576;        // Q hi [d][16]; reused as At re [mk][16]
    float* sQi  = sm + 25600;        //               reused as At im
    float* sQrl = sm + 26624;        // Q lo
    float* sQil = sm + 27648;        // total 28672 floats = 112KB
    int tid = threadIdx.x;
    int base = bh * 4096;

    for (int i = tid; i < 4096; i += 256) {
        float a, b, h;
        a = g_kf_re[base + i]; b = g_kf_re[FDM + base + i]; h = a + b;
        float krl = g_kf_rel[base + i] + g_kf_rel[FDM + base + i] + tsumErr(a, b, h);
        float krh = h;
        a = g_kf_im[base + i]; b = g_kf_im[FDM + base + i]; h = a + b;
        float kil = g_kf_iml[base + i] + g_kf_iml[FDM + base + i] + tsumErr(a, b, h);
        float kih = h;
        sKr[i] = krh; sKi[i] = kih; sKrl[i] = krl; sKil[i] = kil;
        int d = i >> 6, m = i & 63;
        sKTr[m * 64 + d] = krh + krl;
        sKTi[m * 64 + d] = kih + kil;
    }
    for (int i = tid; i < 1024; i += 256) {
        int d = i >> 4, ml = i & 15;
        int gi = base + d * 64 + c0 + ml;
        float a, b, h;
        a = g_qf_re[gi]; b = g_qf_re[FDM + gi]; h = a + b;
        sQrl[i] = g_qf_rel[gi] + g_qf_rel[FDM + gi] + tsumErr(a, b, h);
        sQr[i] = h;
        a = g_qf_im[gi]; b = g_qf_im[FDM + gi]; h = a + b;
        sQil[i] = g_qf_iml[gi] + g_qf_iml[FDM + gi] + tsumErr(a, b, h);
        sQi[i] = h;
    }
    __syncthreads();

    int mq  = tid >> 4;          // 0..15 (local)
    int mk0 = (tid & 15) * 4;

    // phase A: scores[c0+mq][mk0..+3], compensated complex dot over d
    float srA[4], erA[4], siA[4], eiA[4];
    #pragma unroll
    for (int b = 0; b < 4; b++) { srA[b]=0.f; erA[b]=0.f; siA[b]=0.f; eiA[b]=0.f; }

    for (int d = 0; d < 64; d++) {
        float qrh = sQr [d * 16 + mq];
        float qih = sQi [d * 16 + mq];
        float qrl = sQrl[d * 16 + mq];
        float qil = sQil[d * 16 + mq];
        float4 krh4 = *(float4*)(sKr  + d * 64 + mk0);
        float4 kih4 = *(float4*)(sKi  + d * 64 + mk0);
        float4 krl4 = *(float4*)(sKrl + d * 64 + mk0);
        float4 kil4 = *(float4*)(sKil + d * 64 + mk0);
        float krh[4] = {krh4.x, krh4.y, krh4.z, krh4.w};
        float kih[4] = {kih4.x, kih4.y, kih4.z, kih4.w};
        float krl[4] = {krl4.x, krl4.y, krl4.z, krl4.w};
        float kil[4] = {kil4.x, kil4.y, kil4.z, kil4.w};
        #pragma unroll
        for (int b = 0; b < 4; b++) {
            dfAddProd(qrh,  krh[b], srA[b], erA[b]);
            dfAddProd(-qih, kih[b], srA[b], erA[b]);
            erA[b] = fmaf(qrh,  krl[b], erA[b]);
            erA[b] = fmaf(qrl,  krh[b], erA[b]);
            erA[b] = fmaf(-qih, kil[b], erA[b]);
            erA[b] = fmaf(-qil, kih[b], erA[b]);
            dfAddProd(qrh, kih[b], siA[b], eiA[b]);
            dfAddProd(qih, krh[b], siA[b], eiA[b]);
            eiA[b] = fmaf(qrh, kil[b], eiA[b]);
            eiA[b] = fmaf(qrl, kih[b], eiA[b]);
            eiA[b] = fmaf(qih, krl[b], eiA[b]);
            eiA[b] = fmaf(qil, krh[b], eiA[b]);
        }
    }

    // complex tanh (stable form) — numerics identical to R2 kernel
    float tr[4], tim[4];
    #pragma unroll
    for (int b = 0; b < 4; b++) {
        float x2 = 2.f * (srA[b] + erA[b]);
        float y2 = 2.f * (siA[b] + eiA[b]);
        float rr, im;
        if (fabsf(x2) > 30.f) {
            rr = x2 > 0.f ? 1.f : -1.f;
            im = 0.f;
        } else {
            float den = coshf(x2) + cosf(y2);
            rr = sinhf(x2) / den;
            im = sinf(y2) / den;
        }
        tr[b] = rr; tim[b] = im;
    }
    __syncthreads();
    // store attn transposed: At[mk][mq_local]
    #pragma unroll
    for (int b = 0; b < 4; b++) {
        sQr[(mk0 + b) * 16 + mq] = tr[b];
        sQi[(mk0 + b) * 16 + mq] = tim[b];
    }
    __syncthreads();

    // phase B: ctx[c0+mq][d0..+3] = sum_mk At[mk][mq] * KT[mk][d], f32x2-packed
    int d0 = mk0;
    ull cr2[2] = {0ULL, 0ULL}, ci2[2] = {0ULL, 0ULL};
    for (int mk = 0; mk < 64; mk++) {
        float arv = sQr[mk * 16 + mq];
        float aiv = sQi[mk * 16 + mq];
        ull ar  = pk2(arv, arv);
        ull aip = pk2(aiv, aiv);
        ull nai = pk2(-aiv, -aiv);
        ulonglong2 kr = *(ulonglong2*)(sKTr + mk * 64 + d0);
        ulonglong2 ki = *(ulonglong2*)(sKTi + mk * 64 + d0);
        fma2(cr2[0], ar, kr.x);  fma2(cr2[1], ar, kr.y);
        fma2(cr2[0], nai, ki.x); fma2(cr2[1], nai, ki.y);
        fma2(ci2[0], ar, ki.x);  fma2(ci2[1], ar, ki.y);
        fma2(ci2[0], aip, kr.x); fma2(ci2[1], aip, kr.y);
    }
    float v0, v1;
    int obase = base + (c0 + mq) * 64 + d0;
    upk2(cr2[0], v0, v1); g_ctx_re[obase]     = v0; g_ctx_re[obase + 1] = v1;
    upk2(cr2[1], v0, v1); g_ctx_re[obase + 2] = v0; g_ctx_re[obase + 3] = v1;
    upk2(ci2[0], v0, v1); g_ctx_im[obase]     = v0; g_ctx_im[obase + 1] = v1;
    upk2(ci2[1], v0, v1); g_ctx_im[obase + 2] = v0; g_ctx_im[obase + 3] = v1;
}

// ---------------- K3: per-mode complex weight mix ----------------
__global__ __launch_bounds__(256) void k_wmix() {
    int bid = blockIdx.x;
    int h = bid >> 6, qm = bid & 63;
    __shared__ float wr_s[4096];
    __shared__ float wi_s[4096];
    __shared__ float cvr[8][64];
    __shared__ float cvi[8][64];
    int tid = threadIdx.x;
    const float* wrp = g_wt_re + ((size_t)h * 64 + qm) * 4096;
    const float* wip = g_wt_im + ((size_t)h * 64 + qm) * 4096;
    #pragma unroll
    for (int i = 0; i < 4; i++) {
        ((float4*)wr_s)[tid + i * 256] = ((const float4*)wrp)[tid + i * 256];
        ((float4*)wi_s)[tid + i * 256] = ((const float4*)wip)[tid + i * 256];
    }
    for (int i = tid; i < 512; i += 256) {
        int b = i >> 6, ii = i & 63;
        int bh = b * TH + h;
        cvr[b][ii] = g_ctx_re[(bh * 64 + qm) * 64 + ii];
        cvi[b][ii] = g_ctx_im[(bh * 64 + qm) * 64 + ii];
    }
    __syncthreads();
    int b4 = tid >> 6;
    int j = tid & 63;
    #pragma unroll
    for (int bb = 0; bb < 2; bb++) {
        int b = bb * 4 + b4;
        float re = 0.f, im = 0.f;
        #pragma unroll 8
        for (int i = 0; i < 64; i++) {
            float wr = wr_s[i * 64 + j];
            float wi = wi_s[i * 64 + j];
            float crv = cvr[b][i];
            float civ = cvi[b][i];
            re += crv * wr - civ * wi;
            im += crv * wi + civ * wr;
        }
        int bh = b * TH + h;
        g_c2_re[(bh * 64 + qm) * 64 + j] = re;
        g_c2_im[(bh * 64 + qm) * 64 + j] = im;
    }
}

// ---------------- K4: sparse irfft (64 modes -> 1024 samples), f32x2 d-packed ----------------
__global__ __launch_bounds__(256) void k_irfft(float* __restrict__ out) {
    int bh = blockIdx.x;
    int tbase = blockIdx.y * 128;
    extern __shared__ float smArr[];
    float* ar_s = smArr;          // [m][d]
    float* ai_s = smArr + 4096;
    float* c_s  = smArr + 8192;   // [m][128]
    float* s_s  = smArr + 16384;
    int tid = threadIdx.x;

    #pragma unroll
    for (int i = 0; i < 4; i++) {
        int idx = tid + i * 256;
        ((float4*)ar_s)[idx] = ((const float4*)(g_c2_re + bh * 4096))[idx];
        ((float4*)ai_s)[idx] = ((const float4*)(g_c2_im + bh * 4096))[idx];
    }
    #pragma unroll
    for (int i = 0; i < 8; i++) {
        int idx = tid + i * 256;
        int m = idx >> 5, c4 = idx & 31;
        ((float4*)c_s)[idx] = *(const float4*)(g_cosM + m * TL + tbase + c4 * 4);
        ((float4*)s_s)[idx] = *(const float4*)(g_sinM + m * TL + tbase + c4 * 4);
    }
    __syncthreads();

    int tx = tid & 31, ty = tid >> 5;
    int t0 = tx * 4, d0 = ty * 8;

    ull acc2[4][4];  // [d-pair][t]
    #pragma unroll
    for (int a = 0; a < 4; a++)
        #pragma unroll
        for (int b = 0; b < 4; b++) acc2[a][b] = 0ULL;

    for (int m = 1; m < 64; m++) {
        ulonglong2 arA = *(ulonglong2*)(ar_s + m * 64 + d0);
        ulonglong2 arB = *(ulonglong2*)(ar_s + m * 64 + d0 + 4);
        ulonglong2 aiA = *(ulonglong2*)(ai_s + m * 64 + d0);
        ulonglong2 aiB = *(ulonglong2*)(ai_s + m * 64 + d0 + 4);
        ull ar2[4] = {arA.x, arA.y, arB.x, arB.y};
        ull ai2[4] = {aiA.x, aiA.y, aiB.x, aiB.y};
        float4 cv = *(float4*)(c_s + m * 128 + t0);
        float4 sv = *(float4*)(s_s + m * 128 + t0);
        ull cd[4]  = {pk2(cv.x, cv.x), pk2(cv.y, cv.y), pk2(cv.z, cv.z), pk2(cv.w, cv.w)};
        ull nsd[4] = {pk2(-sv.x, -sv.x), pk2(-sv.y, -sv.y), pk2(-sv.z, -sv.z), pk2(-sv.w, -sv.w)};
        #pragma unroll
        for (int a = 0; a < 4; a++)
            #pragma unroll
            for (int b = 0; b < 4; b++) {
                fma2(acc2[a][b], ar2[a], cd[b]);
                fma2(acc2[a][b], ai2[a], nsd[b]);
            }
    }

    const float C0 = 1.0f / 268435456.0f;  // 1/(1024*512*512)
    const float C2 = 2.0f * C0;
    float r[8][4];
    #pragma unroll
    for (int a = 0; a < 4; a++)
        #pragma unroll
        for (int b = 0; b < 4; b++) {
            float lo, hi;
            upk2(acc2[a][b], lo, hi);
            r[2*a][b] = lo; r[2*a+1][b] = hi;
        }
    #pragma unroll
    for (int j = 0; j < 8; j++) {
        float a0 = ar_s[d0 + j];  // m=0 row; imag of bin 0 dropped by irfft
        float4 o;
        o.x = fmaf(C2, r[j][0], C0 * a0);
        o.y = fmaf(C2, r[j][1], C0 * a0);
        o.z = fmaf(C2, r[j][2], C0 * a0);
        o.w = fmaf(C2, r[j][3], C0 * a0);
        *(float4*)(out + ((size_t)bh * 64 + d0 + j) * 1024 + tbase + t0) = o;
    }
}

// ---------------- launch ----------------
extern "C" void kernel_launch(void* const* d_in, const int* in_sizes, int n_in,
                              void* d_out, int out_size) {
    const float* q  = (const float*)d_in[0];
    const float* k  = (const float*)d_in[1];
    const float* wr = (const float*)d_in[3];
    const float* wi = (const float*)d_in[4];
    float* out = (float*)d_out;
    (void)in_sizes; (void)n_in; (void)out_size;

    cudaFuncSetAttribute(k_scores, cudaFuncAttributeMaxDynamicSharedMemorySize, 120 * 1024);
    cudaFuncSetAttribute(k_irfft,  cudaFuncAttributeMaxDynamicSharedMemorySize, 96 * 1024);

    k_twiddle<<<256, 256>>>();
    k_wtrans<<<dim3(128, 2, TH), dim3(32, 8)>>>(wr, wi);
    k_fdft<<<dim3(TBH, 2, 2), 256>>>(q, k);
    k_scores<<<dim3(4, TBH), 256, 28672 * 4>>>();
    k_wmix<<<TH * TM, 256>>>();
    k_irfft<<<dim3(TBH, 8), 256, 96 * 1024>>>(out);
}